// round 4
// baseline (speedup 1.0000x reference)
#include <cuda_runtime.h>
#include <cstdint>

// ---------------- problem constants ----------------
#define B_TOT   16384
#define T_HOR   128
#define F_IN    29
#define K_HID   512
#define BTILE   128
#define NTH     1024
#define NCTAS   (B_TOT / BTILE)     // 128, exact
#define TF_STR  (T_HOR * F_IN)      // 3712 floats per batch row

// tanh prescale: 2*log2(e), folded into W1/b1/feedback weights
#define TANH_S  2.8853900817779268f

// ---------------- shared memory layout ----------------
// Bsm: 4 k-chunks x 512 cols x 4 pairs of float2 = 8192 float2 = 64KB
// cps: 256 col-pairs x 8 floats (wf0,wf0',wf1,wf1',wf2,wf2',w2,w2') = 8KB
// part: double-buffered 2 x (4 quarters x 128 rows) floats = 4KB
#define SM_B_F2     8192
#define SM_CP_OFF   (SM_B_F2 * 8)                 // 65536
#define SM_PART_OFF (SM_CP_OFF + 8192)            // 73728
#define SM_TOTAL    (SM_PART_OFF + 2 * 512 * 4)   // 77824 bytes

typedef unsigned long long ull;

static __device__ __forceinline__ uint32_t tf32r(float x) {
    uint32_t r;
    asm("cvt.rna.tf32.f32 %0, %1;" : "=r"(r) : "f"(x));
    return r;
}

// tanh with pre-scaled input zs = 2*log2(e)*z:
// tanh(z) = 1 - 2/(1 + 2^zs).  ~1e-6 accurate.
static __device__ __forceinline__ float fast_tanh_pre(float zs) {
    float e, r;
    asm("ex2.approx.f32 %0, %1;" : "=f"(e) : "f"(zs));
    asm("rcp.approx.f32 %0, %1;" : "=f"(r) : "f"(e + 1.0f));
    return fmaf(-2.0f, r, 1.0f);
}

#define PACK2(d, lo, hi) \
    asm("mov.b64 %0, {%1, %2};" : "=l"(d) : "r"(__float_as_uint(lo)), "r"(__float_as_uint(hi)))
#define UNPACK2(lo, hi, s) \
    asm("mov.b64 {%0, %1}, %2;" : "=r"(lo), "=r"(hi) : "l"(s))
#define FMA2(d, a, b, c) \
    asm("fma.rn.f32x2 %0, %1, %2, %3;" : "=l"(d) : "l"(a), "l"(b), "l"(c))

// non-volatile: pure register op, let ptxas schedule/interleave freely
#define MMA_TF32(d0, d1, d2, d3, a0, a1, a2, a3, b0, b1)                       \
    asm("mma.sync.aligned.m16n8k8.row.col.f32.tf32.tf32.f32 "                  \
        "{%0,%1,%2,%3}, {%4,%5,%6,%7}, {%8,%9}, {%0,%1,%2,%3};"                \
        : "+f"(d0), "+f"(d1), "+f"(d2), "+f"(d3)                               \
        : "r"(a0), "r"(a1), "r"(a2), "r"(a3), "r"(b0), "r"(b1))

// Load the A fragments (16 tf32 regs) for time step t.
// Rows: rA and rA+8 within the warp tile. Cols: kc*8 + lq, kc*8 + lq + 4.
// Col 29 = 1.0 (bias folded into the GEMM), cols 30/31 = 0.
static __device__ __forceinline__ void loadA(uint32_t a[16], const float* __restrict__ pA,
                                             const float* __restrict__ pB, int t, int lq) {
    const float* xA = pA + t * F_IN;
    const float* xB = pB + t * F_IN;
    #pragma unroll
    for (int kc = 0; kc < 4; ++kc) {
        const int c0 = kc * 8 + lq;          // <= 27, always a real X column
        a[kc * 4 + 0] = tf32r(__ldg(xA + c0));
        a[kc * 4 + 1] = tf32r(__ldg(xB + c0));
        if (kc < 3) {
            const int c1 = c0 + 4;           // <= 23
            a[kc * 4 + 2] = tf32r(__ldg(xA + c1));
            a[kc * 4 + 3] = tf32r(__ldg(xB + c1));
        } else {
            const int c1 = c0 + 4;           // 28..31
            float vA, vB;
            if (c1 < F_IN)       { vA = __ldg(xA + c1); vB = __ldg(xB + c1); }
            else if (c1 == F_IN) { vA = 1.0f; vB = 1.0f; }
            else                 { vA = 0.0f; vB = 0.0f; }
            a[14] = tf32r(vA);
            a[15] = tf32r(vB);
        }
    }
}

__global__ void __launch_bounds__(NTH, 1)
narx_kernel(const float* __restrict__ X, const float* __restrict__ y0,
            const float* __restrict__ W1, const float* __restrict__ b1,
            const float* __restrict__ W2, const float* __restrict__ b2,
            float* __restrict__ out)
{
    extern __shared__ char smem[];
    float2* __restrict__ Bsm  = (float2*)smem;
    float*  __restrict__ cps  = (float*)(smem + SM_CP_OFF);
    float*  __restrict__ part = (float*)(smem + SM_PART_OFF);
    const float4* __restrict__ cp4 = (const float4*)cps;

    const int tid  = threadIdx.x;
    const int w    = tid >> 5;
    const int lane = tid & 31;
    const int lq   = lane & 3;       // quad lane (k / col-pair selector)
    const int lg   = lane >> 2;      // group (row selector)
    const int g    = w & 7;          // row group: rows g*16 .. g*16+15
    const int q    = w >> 3;         // column quarter: cols q*128 .. q*128+127

    // --- stage B operand (pre-scaled by TANH_S): W1 rows 0-28, row 29 = b1, 30/31 = 0 ---
    // float2 idx = kc*2048 + col*4 + p  holds (W[kc*8+p][col], W[kc*8+p+4][col]).
    for (int idx = tid; idx < SM_B_F2; idx += NTH) {
        const int kc = idx >> 11, rem = idx & 2047;
        const int col = rem >> 2, p = rem & 3;
        const int k0 = kc * 8 + p, k1 = k0 + 4;
        float v0 = (k0 < F_IN) ? W1[k0 * K_HID + col] : ((k0 == F_IN) ? b1[col] : 0.0f);
        float v1 = (k1 < F_IN) ? W1[k1 * K_HID + col] : ((k1 == F_IN) ? b1[col] : 0.0f);
        float2 fv;
        fv.x = __uint_as_float(tf32r(v0 * TANH_S));
        fv.y = __uint_as_float(tf32r(v1 * TANH_S));
        Bsm[idx] = fv;
    }
    // --- per-column constants: feedback weights (pre-scaled) + W2 (unscaled) ---
    for (int col = tid; col < K_HID; col += NTH) {
        const int p = col >> 1, s = col & 1;
        cps[p * 8 + 0 + s] = W1[29 * K_HID + col] * TANH_S;
        cps[p * 8 + 2 + s] = W1[30 * K_HID + col] * TANH_S;
        cps[p * 8 + 4 + s] = W1[31 * K_HID + col] * TANH_S;
        cps[p * 8 + 6 + s] = W2[col];
    }
    __syncthreads();

    // --- per-thread row bindings ---
    const int rowLA = g * 16 + lg;          // local rows within the 128-row tile
    const int rowLB = rowLA + 8;
    const int rowGA = blockIdx.x * BTILE + rowLA;
    const int rowGB = rowGA + 8;
    const float* __restrict__ pA = X + (size_t)rowGA * TF_STR;
    const float* __restrict__ pB = X + (size_t)rowGB * TF_STR;
    float* __restrict__ outA = out + (size_t)rowGA * T_HOR;
    float* __restrict__ outB = out + (size_t)rowGB * T_HOR;

    const float b2v = b2[0];

    // packed feedback state (each value duplicated in both halves of the f32x2)
    ull f0ap, f1ap, f2ap, f0bp, f1bp, f2bp;
    {
        float f0a = y0[rowGA * 3 + 0], f1a = y0[rowGA * 3 + 1], f2a = y0[rowGA * 3 + 2];
        float f0b = y0[rowGB * 3 + 0], f1b = y0[rowGB * 3 + 1], f2b = y0[rowGB * 3 + 2];
        PACK2(f0ap, f0a, f0a); PACK2(f1ap, f1a, f1a); PACK2(f2ap, f2a, f2a);
        PACK2(f0bp, f0b, f0b); PACK2(f1bp, f1b, f1b); PACK2(f2bp, f2b, f2b);
    }

    const int ntOfs = q * 16;               // this warp's n-tile offset (16 tiles = 128 cols)

    for (int t = 0; t < T_HOR; ++t) {
        uint32_t aC[16];
        loadA(aC, pA, pB, t, lq);

        ull dotLo, dotHi;
        PACK2(dotLo, 0.0f, 0.0f);
        PACK2(dotHi, 0.0f, 0.0f);

        #pragma unroll 4
        for (int nt = 0; nt < 16; ++nt) {
            const int ntg = ntOfs + nt;      // global n-tile (0..63)
            float d0 = 0.f, d1 = 0.f, d2 = 0.f, d3 = 0.f;
            #pragma unroll
            for (int kc = 0; kc < 4; ++kc) {
                const float2 bb = Bsm[kc * 2048 + ntg * 32 + lane];
                MMA_TF32(d0, d1, d2, d3,
                         aC[kc * 4 + 0], aC[kc * 4 + 1], aC[kc * 4 + 2], aC[kc * 4 + 3],
                         __float_as_uint(bb.x), __float_as_uint(bb.y));
            }
            // epilogue on this 2x2 accum fragment: cols (c0,c1) = ntg*8 + 2*lq (+1)
            const int pidx = ntg * 4 + lq;
            const float4 q0 = cp4[2 * pidx + 0];  // wf0[c0],wf0[c1],wf1[c0],wf1[c1] (scaled)
            const float4 q1 = cp4[2 * pidx + 1];  // wf2[c0],wf2[c1],w2[c0], w2[c1]
            ull zlo, zhi, wp;
            PACK2(zlo, d0, d1);
            PACK2(zhi, d2, d3);
            PACK2(wp, q0.x, q0.y); FMA2(zlo, wp, f0ap, zlo); FMA2(zhi, wp, f0bp, zhi);
            PACK2(wp, q0.z, q0.w); FMA2(zlo, wp, f1ap, zlo); FMA2(zhi, wp, f1bp, zhi);
            PACK2(wp, q1.x, q1.y); FMA2(zlo, wp, f2ap, zlo); FMA2(zhi, wp, f2bp, zhi);
            uint32_t u0, u1, u2, u3;
            UNPACK2(u0, u1, zlo);
            UNPACK2(u2, u3, zhi);
            const float h0 = fast_tanh_pre(__uint_as_float(u0));
            const float h1 = fast_tanh_pre(__uint_as_float(u1));
            const float h2 = fast_tanh_pre(__uint_as_float(u2));
            const float h3 = fast_tanh_pre(__uint_as_float(u3));
            ull hlo, hhi;
            PACK2(hlo, h0, h1);
            PACK2(hhi, h2, h3);
            PACK2(wp, q1.z, q1.w);
            FMA2(dotLo, hlo, wp, dotLo);
            FMA2(dotHi, hhi, wp, dotHi);
        }

        // reduce dot over the quad (cols) -> this quarter's partial for rows rA, rA+8
        uint32_t s0, s1;
        UNPACK2(s0, s1, dotLo);
        float sLo = __uint_as_float(s0) + __uint_as_float(s1);
        UNPACK2(s0, s1, dotHi);
        float sHi = __uint_as_float(s0) + __uint_as_float(s1);
        sLo += __shfl_xor_sync(0xffffffffu, sLo, 1);
        sLo += __shfl_xor_sync(0xffffffffu, sLo, 2);
        sHi += __shfl_xor_sync(0xffffffffu, sHi, 1);
        sHi += __shfl_xor_sync(0xffffffffu, sHi, 2);

        // cross-quarter combine via double-buffered SMEM partials + one barrier
        float* pbuf = part + (t & 1) * 512;
        if (lq == 0) {
            pbuf[q * 128 + rowLA] = sLo;
            pbuf[q * 128 + rowLB] = sHi;
        }
        __syncthreads();
        const float predLo = pbuf[rowLA] + pbuf[128 + rowLA]
                           + pbuf[256 + rowLA] + pbuf[384 + rowLA] + b2v;
        const float predHi = pbuf[rowLB] + pbuf[128 + rowLB]
                           + pbuf[256 + rowLB] + pbuf[384 + rowLB] + b2v;
        if (q == 0 && lq == 0) {
            outA[t] = predLo;
            outB[t] = predHi;
        }
        // shift feedback: fb2 <- fb1 <- fb0 <- pred
        f2ap = f1ap; f1ap = f0ap; PACK2(f0ap, predLo, predLo);
        f2bp = f1bp; f1bp = f0bp; PACK2(f0bp, predHi, predHi);
    }
}

extern "C" void kernel_launch(void* const* d_in, const int* in_sizes, int n_in,
                              void* d_out, int out_size) {
    const float* X  = (const float*)d_in[0];
    const float* y0 = (const float*)d_in[1];
    const float* W1 = (const float*)d_in[2];
    const float* b1 = (const float*)d_in[3];
    const float* W2 = (const float*)d_in[4];
    const float* b2 = (const float*)d_in[5];
    float* out = (float*)d_out;
    (void)in_sizes; (void)n_in; (void)out_size;

    cudaFuncSetAttribute(narx_kernel, cudaFuncAttributeMaxDynamicSharedMemorySize, SM_TOTAL);
    narx_kernel<<<NCTAS, NTH, SM_TOTAL>>>(X, y0, W1, b1, W2, b2, out);
}

// round 5
// speedup vs baseline: 1.4302x; 1.4302x over previous
#include <cuda_runtime.h>
#include <cstdint>

// ---------------- problem constants ----------------
#define B_TOT   16384
#define T_HOR   128
#define F_IN    29
#define K_HID   512
#define BTILE   128
#define NTH     1024
#define NCTAS   (B_TOT / BTILE)     // 128, exact
#define TF_STR  (T_HOR * F_IN)      // 3712 floats per batch row

// ---------------- shared memory layout ----------------
// Bsm: 4 k-chunks x 512 cols x 4 pairs of float2 = 8192 float2 = 64KB
//      (now holds ALL 32 rows of W1: X rows 0-28 AND feedback rows 29-31)
// cps: 256 col-pairs x float4 (b1[c0], b1[c1], w2[c0], w2[c1]) = 4KB
// part: double-buffered 2 x (4 quarters x 128 rows) floats = 4KB
#define SM_B_F2     8192
#define SM_CP_OFF   (SM_B_F2 * 8)                 // 65536
#define SM_PART_OFF (SM_CP_OFF + 4096)            // 69632
#define SM_TOTAL    (SM_PART_OFF + 2 * 512 * 4)   // 73728 bytes

static __device__ __forceinline__ uint32_t tf32r(float x) {
    uint32_t r;
    asm("cvt.rna.tf32.f32 %0, %1;" : "=r"(r) : "f"(x));
    return r;
}

static __device__ __forceinline__ float tanh_fast(float z) {
    float h;
    asm("tanh.approx.f32 %0, %1;" : "=f"(h) : "f"(z));
    return h;
}

// non-volatile: pure register op, let ptxas schedule/interleave freely
#define MMA_TF32(d0, d1, d2, d3, a0, a1, a2, a3, b0, b1)                       \
    asm("mma.sync.aligned.m16n8k8.row.col.f32.tf32.tf32.f32 "                  \
        "{%0,%1,%2,%3}, {%4,%5,%6,%7}, {%8,%9}, {%0,%1,%2,%3};"                \
        : "+f"(d0), "+f"(d1), "+f"(d2), "+f"(d3)                               \
        : "r"(a0), "r"(a1), "r"(a2), "r"(a3), "r"(b0), "r"(b1))

// Load A fragments (16 tf32 regs) for time step t.
// Rows rA=lg, rB=lg+8. Cols: kc*8+lq and kc*8+lq+4.
// For kc==3, c1 = 28+lq: lq==0 -> X col 28; lq==1/2/3 -> feedback fb0/fb1/fb2
// (passed in as pre-rounded tf32 regs fbA/fbB, selected per-thread).
static __device__ __forceinline__ void loadA(uint32_t a[16], const float* __restrict__ pA,
                                             const float* __restrict__ pB, int t, int lq,
                                             uint32_t fbA, uint32_t fbB) {
    const float* xA = pA + t * F_IN;
    const float* xB = pB + t * F_IN;
    #pragma unroll
    for (int kc = 0; kc < 4; ++kc) {
        const int c0 = kc * 8 + lq;          // <= 27, always a real X column
        a[kc * 4 + 0] = tf32r(__ldg(xA + c0));
        a[kc * 4 + 1] = tf32r(__ldg(xB + c0));
        if (kc < 3) {
            const int c1 = c0 + 4;           // <= 23
            a[kc * 4 + 2] = tf32r(__ldg(xA + c1));
            a[kc * 4 + 3] = tf32r(__ldg(xB + c1));
        }
    }
    if (lq == 0) {
        a[14] = tf32r(__ldg(xA + 28));
        a[15] = tf32r(__ldg(xB + 28));
    } else {
        a[14] = fbA;
        a[15] = fbB;
    }
}

__global__ void __launch_bounds__(NTH, 1)
narx_kernel(const float* __restrict__ X, const float* __restrict__ y0,
            const float* __restrict__ W1, const float* __restrict__ b1,
            const float* __restrict__ W2, const float* __restrict__ b2,
            float* __restrict__ out)
{
    extern __shared__ char smem[];
    float2* __restrict__ Bsm  = (float2*)smem;
    float4* __restrict__ cp4  = (float4*)(smem + SM_CP_OFF);
    float*  __restrict__ part = (float*)(smem + SM_PART_OFF);

    const int tid  = threadIdx.x;
    const int w    = tid >> 5;
    const int lane = tid & 31;
    const int lq   = lane & 3;       // quad lane (k / col-pair selector)
    const int lg   = lane >> 2;      // group (row selector)
    const int g    = w & 7;          // row group: rows g*16 .. g*16+15
    const int q    = w >> 3;         // column quarter: cols q*128 .. q*128+127

    // --- stage B operand: ALL 32 W1 rows (0-28 = X weights, 29-31 = feedback weights) ---
    // float2 idx = kc*2048 + col*4 + p  holds (W1[kc*8+p][col], W1[kc*8+p+4][col]).
    for (int idx = tid; idx < SM_B_F2; idx += NTH) {
        const int kc = idx >> 11, rem = idx & 2047;
        const int col = rem >> 2, p = rem & 3;
        const int k0 = kc * 8 + p, k1 = k0 + 4;   // both < 32, always valid
        float2 fv;
        fv.x = __uint_as_float(tf32r(W1[k0 * K_HID + col]));
        fv.y = __uint_as_float(tf32r(W1[k1 * K_HID + col]));
        Bsm[idx] = fv;
    }
    // --- per-col-pair constants: (b1[c0], b1[c1], w2[c0], w2[c1]) ---
    for (int p = tid; p < K_HID / 2; p += NTH) {
        float4 c;
        c.x = b1[2 * p];
        c.y = b1[2 * p + 1];
        c.z = W2[2 * p];
        c.w = W2[2 * p + 1];
        cp4[p] = c;
    }
    __syncthreads();

    // --- per-thread row bindings ---
    const int rowLA = g * 16 + lg;          // local rows within the 128-row tile
    const int rowLB = rowLA + 8;
    const int rowGA = blockIdx.x * BTILE + rowLA;
    const int rowGB = rowGA + 8;
    const float* __restrict__ pA = X + (size_t)rowGA * TF_STR;
    const float* __restrict__ pB = X + (size_t)rowGB * TF_STR;
    float* __restrict__ outA = out + (size_t)rowGA * T_HOR;
    float* __restrict__ outB = out + (size_t)rowGB * T_HOR;

    const float b2v = b2[0];

    // feedback state (fp32) + per-thread tf32 selection for the A fragment
    float f0a = y0[rowGA * 3 + 0], f1a = y0[rowGA * 3 + 1], f2a = y0[rowGA * 3 + 2];
    float f0b = y0[rowGB * 3 + 0], f1b = y0[rowGB * 3 + 1], f2b = y0[rowGB * 3 + 2];
    uint32_t fbA = tf32r((lq == 1) ? f0a : (lq == 2) ? f1a : f2a);
    uint32_t fbB = tf32r((lq == 1) ? f0b : (lq == 2) ? f1b : f2b);

    const int ntOfs = q * 16;               // this warp's n-tile offset (16 tiles = 128 cols)

    for (int t = 0; t < T_HOR; ++t) {
        uint32_t aC[16];
        loadA(aC, pA, pB, t, lq, fbA, fbB);

        float dotA = 0.0f, dotB = 0.0f;

        #pragma unroll 4
        for (int nt = 0; nt < 16; ++nt) {
            const int ntg = ntOfs + nt;      // global n-tile (0..63)
            // constants for cols c0 = ntg*8+2lq, c1 = c0+1
            const float4 qc = cp4[ntg * 4 + lq];
            // accumulator initialized with the bias -> no epilogue FADD
            float d0 = qc.x, d1 = qc.y, d2 = qc.x, d3 = qc.y;
            #pragma unroll
            for (int kc = 0; kc < 4; ++kc) {
                const float2 bb = Bsm[kc * 2048 + ntg * 32 + lane];
                MMA_TF32(d0, d1, d2, d3,
                         aC[kc * 4 + 0], aC[kc * 4 + 1], aC[kc * 4 + 2], aC[kc * 4 + 3],
                         __float_as_uint(bb.x), __float_as_uint(bb.y));
            }
            // tanh + dot with W2
            const float h0 = tanh_fast(d0);
            const float h1 = tanh_fast(d1);
            const float h2 = tanh_fast(d2);
            const float h3 = tanh_fast(d3);
            dotA = fmaf(h0, qc.z, dotA);
            dotA = fmaf(h1, qc.w, dotA);
            dotB = fmaf(h2, qc.z, dotB);
            dotB = fmaf(h3, qc.w, dotB);
        }

        // quad reduce (over the 8 cols each quad member covers)
        dotA += __shfl_xor_sync(0xffffffffu, dotA, 1);
        dotA += __shfl_xor_sync(0xffffffffu, dotA, 2);
        dotB += __shfl_xor_sync(0xffffffffu, dotB, 1);
        dotB += __shfl_xor_sync(0xffffffffu, dotB, 2);

        // cross-quarter combine via double-buffered SMEM partials + one barrier
        float* pbuf = part + (t & 1) * 512;
        if (lq == 0) {
            pbuf[q * 128 + rowLA] = dotA;
            pbuf[q * 128 + rowLB] = dotB;
        }
        __syncthreads();
        const float predLo = pbuf[rowLA] + pbuf[128 + rowLA]
                           + pbuf[256 + rowLA] + pbuf[384 + rowLA] + b2v;
        const float predHi = pbuf[rowLB] + pbuf[128 + rowLB]
                           + pbuf[256 + rowLB] + pbuf[384 + rowLB] + b2v;
        if (q == 0 && lq == 0) {
            outA[t] = predLo;
            outB[t] = predHi;
        }
        // shift feedback: fb2 <- fb1 <- fb0 <- pred; refresh tf32 selections
        f2a = f1a; f1a = f0a; f0a = predLo;
        f2b = f1b; f1b = f0b; f0b = predHi;
        fbA = tf32r((lq == 1) ? f0a : (lq == 2) ? f1a : f2a);
        fbB = tf32r((lq == 1) ? f0b : (lq == 2) ? f1b : f2b);
    }
}

extern "C" void kernel_launch(void* const* d_in, const int* in_sizes, int n_in,
                              void* d_out, int out_size) {
    const float* X  = (const float*)d_in[0];
    const float* y0 = (const float*)d_in[1];
    const float* W1 = (const float*)d_in[2];
    const float* b1 = (const float*)d_in[3];
    const float* W2 = (const float*)d_in[4];
    const float* b2 = (const float*)d_in[5];
    float* out = (float*)d_out;
    (void)in_sizes; (void)n_in; (void)out_size;

    cudaFuncSetAttribute(narx_kernel, cudaFuncAttributeMaxDynamicSharedMemorySize, SM_TOTAL);
    narx_kernel<<<NCTAS, NTH, SM_TOTAL>>>(X, y0, W1, b1, W2, b2, out);
}

// round 6
// speedup vs baseline: 1.4438x; 1.0095x over previous
#include <cuda_runtime.h>
#include <cstdint>

// ---------------- problem constants ----------------
#define B_TOT   16384
#define T_HOR   128
#define F_IN    29
#define K_HID   512
#define BTILE   128
#define NTH     512
#define NCTAS   (B_TOT / BTILE)     // 128, exact
#define TF_STR  (T_HOR * F_IN)      // 3712 floats per batch row

// ---------------- shared memory layout ----------------
// Bsm: 4 k-chunks x 512 cols x 4 pairs of float2 = 8192 float2 = 64KB
//      (ALL 32 rows of W1: X rows 0-28 AND feedback rows 29-31)
// cps: 256 col-pairs x float4 (b1[c0], b1[c1], w2[c0], w2[c1]) = 4KB
// part: double-buffered 2 x (4 quarters x 128 rows) floats = 4KB
#define SM_B_F2     8192
#define SM_CP_OFF   (SM_B_F2 * 8)                 // 65536
#define SM_PART_OFF (SM_CP_OFF + 4096)            // 69632
#define SM_TOTAL    (SM_PART_OFF + 2 * 512 * 4)   // 73728 bytes

static __device__ __forceinline__ uint32_t tf32r(float x) {
    uint32_t r;
    asm("cvt.rna.tf32.f32 %0, %1;" : "=r"(r) : "f"(x));
    return r;
}

static __device__ __forceinline__ float tanh_fast(float z) {
    float h;
    asm("tanh.approx.f32 %0, %1;" : "=f"(h) : "f"(z));
    return h;
}

// non-volatile: pure register op, let ptxas schedule/interleave freely
#define MMA_TF32(d0, d1, d2, d3, a0, a1, a2, a3, b0, b1)                       \
    asm("mma.sync.aligned.m16n8k8.row.col.f32.tf32.tf32.f32 "                  \
        "{%0,%1,%2,%3}, {%4,%5,%6,%7}, {%8,%9}, {%0,%1,%2,%3};"                \
        : "+f"(d0), "+f"(d1), "+f"(d2), "+f"(d3)                               \
        : "r"(a0), "r"(a1), "r"(a2), "r"(a3), "r"(b0), "r"(b1))

// Load one A fragment set (16 tf32 regs) for rows (rX, rX+8) at time t.
// Cols: kc*8+lq and kc*8+lq+4. For kc==3, c1 = 28+lq:
//   lq==0 -> X col 28;  lq==1/2/3 -> feedback fb0/fb1/fb2 (pre-rounded tf32).
static __device__ __forceinline__ void loadA(uint32_t a[16], const float* __restrict__ pA,
                                             const float* __restrict__ pB, int t, int lq,
                                             uint32_t fbA, uint32_t fbB) {
    const float* xA = pA + t * F_IN;
    const float* xB = pB + t * F_IN;
    #pragma unroll
    for (int kc = 0; kc < 4; ++kc) {
        const int c0 = kc * 8 + lq;          // <= 27, always a real X column
        a[kc * 4 + 0] = tf32r(__ldg(xA + c0));
        a[kc * 4 + 1] = tf32r(__ldg(xB + c0));
        if (kc < 3) {
            const int c1 = c0 + 4;           // <= 23
            a[kc * 4 + 2] = tf32r(__ldg(xA + c1));
            a[kc * 4 + 3] = tf32r(__ldg(xB + c1));
        }
    }
    if (lq == 0) {
        a[14] = tf32r(__ldg(xA + 28));
        a[15] = tf32r(__ldg(xB + 28));
    } else {
        a[14] = fbA;
        a[15] = fbB;
    }
}

__global__ void __launch_bounds__(NTH, 1)
narx_kernel(const float* __restrict__ X, const float* __restrict__ y0,
            const float* __restrict__ W1, const float* __restrict__ b1,
            const float* __restrict__ W2, const float* __restrict__ b2,
            float* __restrict__ out)
{
    extern __shared__ char smem[];
    float2* __restrict__ Bsm  = (float2*)smem;
    float4* __restrict__ cp4  = (float4*)(smem + SM_CP_OFF);
    float*  __restrict__ part = (float*)(smem + SM_PART_OFF);

    const int tid  = threadIdx.x;
    const int w    = tid >> 5;
    const int lane = tid & 31;
    const int lq   = lane & 3;       // quad lane (k / col-pair selector)
    const int lg   = lane >> 2;      // group (row selector)
    const int g    = w & 3;          // row group: rows g*32 .. g*32+31
    const int q    = w >> 2;         // column quarter: cols q*128 .. q*128+127

    // --- stage B operand: ALL 32 W1 rows ---
    // float2 idx = kc*2048 + col*4 + p  holds (W1[kc*8+p][col], W1[kc*8+p+4][col]).
    for (int idx = tid; idx < SM_B_F2; idx += NTH) {
        const int kc = idx >> 11, rem = idx & 2047;
        const int col = rem >> 2, p = rem & 3;
        const int k0 = kc * 8 + p, k1 = k0 + 4;
        float2 fv;
        fv.x = __uint_as_float(tf32r(W1[k0 * K_HID + col]));
        fv.y = __uint_as_float(tf32r(W1[k1 * K_HID + col]));
        Bsm[idx] = fv;
    }
    // --- per-col-pair constants: (b1[c0], b1[c1], w2[c0], w2[c1]) ---
    for (int p = tid; p < K_HID / 2; p += NTH) {
        float4 c;
        c.x = b1[2 * p];
        c.y = b1[2 * p + 1];
        c.z = W2[2 * p];
        c.w = W2[2 * p + 1];
        cp4[p] = c;
    }
    __syncthreads();

    // --- per-thread row bindings: 4 rows per thread ---
    const int rowLA = g * 32 + lg;          // set0: rows rowLA, rowLA+8
    const int rowLC = rowLA + 16;           // set1: rows rowLC, rowLC+8
    const int rowGA = blockIdx.x * BTILE + rowLA;
    const int rowGC = rowGA + 16;
    const float* __restrict__ pA = X + (size_t)rowGA * TF_STR;
    const float* __restrict__ pB = pA + 8 * TF_STR;
    const float* __restrict__ pC = X + (size_t)rowGC * TF_STR;
    const float* __restrict__ pD = pC + 8 * TF_STR;
    float* __restrict__ outA = out + (size_t)rowGA * T_HOR;

    const float b2v = b2[0];

    // feedback state for 4 rows
    float f0a = y0[rowGA * 3 + 0], f1a = y0[rowGA * 3 + 1], f2a = y0[rowGA * 3 + 2];
    float f0b = y0[(rowGA + 8) * 3 + 0], f1b = y0[(rowGA + 8) * 3 + 1], f2b = y0[(rowGA + 8) * 3 + 2];
    float f0c = y0[rowGC * 3 + 0], f1c = y0[rowGC * 3 + 1], f2c = y0[rowGC * 3 + 2];
    float f0d = y0[(rowGC + 8) * 3 + 0], f1d = y0[(rowGC + 8) * 3 + 1], f2d = y0[(rowGC + 8) * 3 + 2];
    uint32_t fbA = tf32r((lq == 1) ? f0a : (lq == 2) ? f1a : f2a);
    uint32_t fbB = tf32r((lq == 1) ? f0b : (lq == 2) ? f1b : f2b);
    uint32_t fbC = tf32r((lq == 1) ? f0c : (lq == 2) ? f1c : f2c);
    uint32_t fbD = tf32r((lq == 1) ? f0d : (lq == 2) ? f1d : f2d);

    const int ntOfs = q * 16;               // this warp's n-tile offset (16 tiles = 128 cols)

    for (int t = 0; t < T_HOR; ++t) {
        uint32_t a0[16], a1[16];
        loadA(a0, pA, pB, t, lq, fbA, fbB);
        loadA(a1, pC, pD, t, lq, fbC, fbD);

        float dotA = 0.0f, dotB = 0.0f, dotC = 0.0f, dotD = 0.0f;

        #pragma unroll 4
        for (int nt = 0; nt < 16; ++nt) {
            const int ntg = ntOfs + nt;      // global n-tile (0..63)
            const float4 qc = cp4[ntg * 4 + lq];
            float d0 = qc.x, d1 = qc.y, d2 = qc.x, d3 = qc.y;   // set0 (bias-init)
            float e0 = qc.x, e1 = qc.y, e2 = qc.x, e3 = qc.y;   // set1
            #pragma unroll
            for (int kc = 0; kc < 4; ++kc) {
                const float2 bb = Bsm[kc * 2048 + ntg * 32 + lane];
                const uint32_t bx = __float_as_uint(bb.x), by = __float_as_uint(bb.y);
                MMA_TF32(d0, d1, d2, d3,
                         a0[kc * 4 + 0], a0[kc * 4 + 1], a0[kc * 4 + 2], a0[kc * 4 + 3], bx, by);
                MMA_TF32(e0, e1, e2, e3,
                         a1[kc * 4 + 0], a1[kc * 4 + 1], a1[kc * 4 + 2], a1[kc * 4 + 3], bx, by);
            }
            // tanh + dot with W2 (8 independent chains)
            dotA = fmaf(tanh_fast(d0), qc.z, dotA);
            dotA = fmaf(tanh_fast(d1), qc.w, dotA);
            dotB = fmaf(tanh_fast(d2), qc.z, dotB);
            dotB = fmaf(tanh_fast(d3), qc.w, dotB);
            dotC = fmaf(tanh_fast(e0), qc.z, dotC);
            dotC = fmaf(tanh_fast(e1), qc.w, dotC);
            dotD = fmaf(tanh_fast(e2), qc.z, dotD);
            dotD = fmaf(tanh_fast(e3), qc.w, dotD);
        }

        // quad reduce (over the 8 cols each quad member covers)
        dotA += __shfl_xor_sync(0xffffffffu, dotA, 1);
        dotA += __shfl_xor_sync(0xffffffffu, dotA, 2);
        dotB += __shfl_xor_sync(0xffffffffu, dotB, 1);
        dotB += __shfl_xor_sync(0xffffffffu, dotB, 2);
        dotC += __shfl_xor_sync(0xffffffffu, dotC, 1);
        dotC += __shfl_xor_sync(0xffffffffu, dotC, 2);
        dotD += __shfl_xor_sync(0xffffffffu, dotD, 1);
        dotD += __shfl_xor_sync(0xffffffffu, dotD, 2);

        // cross-quarter combine via double-buffered SMEM partials + one barrier
        float* pbuf = part + (t & 1) * 512;
        if (lq == 0) {
            pbuf[q * 128 + rowLA]      = dotA;
            pbuf[q * 128 + rowLA + 8]  = dotB;
            pbuf[q * 128 + rowLC]      = dotC;
            pbuf[q * 128 + rowLC + 8]  = dotD;
        }
        __syncthreads();
        const float predA = pbuf[rowLA]     + pbuf[128 + rowLA]     + pbuf[256 + rowLA]     + pbuf[384 + rowLA]     + b2v;
        const float predB = pbuf[rowLA + 8] + pbuf[128 + rowLA + 8] + pbuf[256 + rowLA + 8] + pbuf[384 + rowLA + 8] + b2v;
        const float predC = pbuf[rowLC]     + pbuf[128 + rowLC]     + pbuf[256 + rowLC]     + pbuf[384 + rowLC]     + b2v;
        const float predD = pbuf[rowLC + 8] + pbuf[128 + rowLC + 8] + pbuf[256 + rowLC + 8] + pbuf[384 + rowLC + 8] + b2v;
        if (q == 0 && lq == 0) {
            outA[t]               = predA;
            outA[8 * T_HOR + t]   = predB;
            outA[16 * T_HOR + t]  = predC;
            outA[24 * T_HOR + t]  = predD;
        }
        // shift feedback: fb2 <- fb1 <- fb0 <- pred; refresh tf32 selections
        f2a = f1a; f1a = f0a; f0a = predA;
        f2b = f1b; f1b = f0b; f0b = predB;
        f2c = f1c; f1c = f0c; f0c = predC;
        f2d = f1d; f1d = f0d; f0d = predD;
        fbA = tf32r((lq == 1) ? f0a : (lq == 2) ? f1a : f2a);
        fbB = tf32r((lq == 1) ? f0b : (lq == 2) ? f1b : f2b);
        fbC = tf32r((lq == 1) ? f0c : (lq == 2) ? f1c : f2c);
        fbD = tf32r((lq == 1) ? f0d : (lq == 2) ? f1d : f2d);
    }
}

extern "C" void kernel_launch(void* const* d_in, const int* in_sizes, int n_in,
                              void* d_out, int out_size) {
    const float* X  = (const float*)d_in[0];
    const float* y0 = (const float*)d_in[1];
    const float* W1 = (const float*)d_in[2];
    const float* b1 = (const float*)d_in[3];
    const float* W2 = (const float*)d_in[4];
    const float* b2 = (const float*)d_in[5];
    float* out = (float*)d_out;
    (void)in_sizes; (void)n_in; (void)out_size;

    cudaFuncSetAttribute(narx_kernel, cudaFuncAttributeMaxDynamicSharedMemorySize, SM_TOTAL);
    narx_kernel<<<NCTAS, NTH, SM_TOTAL>>>(X, y0, W1, b1, W2, b2, out);
}

// round 7
// speedup vs baseline: 2.1438x; 1.4849x over previous
#include <cuda_runtime.h>
#include <cstdint>

// ---------------- problem constants ----------------
#define B_TOT   16384
#define T_HOR   128
#define F_IN    29
#define K_HID   512
#define BTILE   64
#define NTH     256
#define NCTAS   (B_TOT / BTILE)     // 256
#define TF_STR  (T_HOR * F_IN)      // 3712 floats per batch row

// X stage buffer: 64 rows x stride 36 (pad -> conflict-free quad LDS), double-buffered
#define XSTRIDE 36
#define XBUF    (BTILE * XSTRIDE)   // 2304 floats
#define XELEMS  (BTILE * F_IN)      // 1856 floats per step

// ---------------- shared memory layout ----------------
#define SM_B_F2     8192                          // 64KB: all 32 W1 rows
#define SM_CP_OFF   (SM_B_F2 * 8)                 // 65536: 256 x float4 = 4KB
#define SM_PART_OFF (SM_CP_OFF + 4096)            // 69632: 2 x 256 floats = 2KB
#define SM_X_OFF    (SM_PART_OFF + 2048)          // 71680: 2 x 2304 floats = 18432B
#define SM_TOTAL    (SM_X_OFF + 2 * XBUF * 4)     // 90112 bytes (fits 2 CTAs/SM)

static __device__ __forceinline__ uint32_t tf32r(float x) {
    uint32_t r;
    asm("cvt.rna.tf32.f32 %0, %1;" : "=r"(r) : "f"(x));
    return r;
}

static __device__ __forceinline__ float tanh_fast(float z) {
    float h;
    asm("tanh.approx.f32 %0, %1;" : "=f"(h) : "f"(z));
    return h;
}

// non-volatile: let ptxas schedule/interleave freely
#define MMA_TF32(d0, d1, d2, d3, a0, a1, a2, a3, b0, b1)                       \
    asm("mma.sync.aligned.m16n8k8.row.col.f32.tf32.tf32.f32 "                  \
        "{%0,%1,%2,%3}, {%4,%5,%6,%7}, {%8,%9}, {%0,%1,%2,%3};"                \
        : "+f"(d0), "+f"(d1), "+f"(d2), "+f"(d3)                               \
        : "r"(a0), "r"(a1), "r"(a2), "r"(a3), "r"(b0), "r"(b1))

// fast div by 29 for j < 16384:  row = (j*565) >> 14
static __device__ __forceinline__ int div29(int j) { return (j * 565) >> 14; }

// Load one A fragment set (16 tf32 regs) for rows (rA, rA+8) from the SMEM X stage.
// Cols: kc*8+lq and kc*8+lq+4. For kc==3, c1 = 28+lq:
//   lq==0 -> X col 28;  lq==1/2/3 -> feedback fb0/fb1/fb2 (pre-rounded tf32).
static __device__ __forceinline__ void loadA_sm(uint32_t a[16], const float* __restrict__ Xc,
                                                int rA, int lq, uint32_t fbA, uint32_t fbB) {
    const float* xA = Xc + rA * XSTRIDE;
    const float* xB = xA + 8 * XSTRIDE;
    #pragma unroll
    for (int kc = 0; kc < 4; ++kc) {
        const int c0 = kc * 8 + lq;          // <= 27
        a[kc * 4 + 0] = __float_as_uint(xA[c0]);
        a[kc * 4 + 1] = __float_as_uint(xB[c0]);
        if (kc < 3) {
            const int c1 = c0 + 4;           // <= 23
            a[kc * 4 + 2] = __float_as_uint(xA[c1]);
            a[kc * 4 + 3] = __float_as_uint(xB[c1]);
        }
    }
    if (lq == 0) {
        a[14] = __float_as_uint(xA[28]);
        a[15] = __float_as_uint(xB[28]);
    } else {
        a[14] = fbA;
        a[15] = fbB;
    }
}

__global__ void __launch_bounds__(NTH, 2)
narx_kernel(const float* __restrict__ X, const float* __restrict__ y0,
            const float* __restrict__ W1, const float* __restrict__ b1,
            const float* __restrict__ W2, const float* __restrict__ b2,
            float* __restrict__ out)
{
    extern __shared__ char smem[];
    float2* __restrict__ Bsm  = (float2*)smem;
    float4* __restrict__ cp4  = (float4*)(smem + SM_CP_OFF);
    float*  __restrict__ part = (float*)(smem + SM_PART_OFF);
    float*  __restrict__ Xs   = (float*)(smem + SM_X_OFF);

    const int tid  = threadIdx.x;
    const int w    = tid >> 5;
    const int lane = tid & 31;
    const int lq   = lane & 3;       // quad lane (k / col-pair selector)
    const int lg   = lane >> 2;      // group (row selector)
    const int g    = w & 1;          // row group: rows g*32 .. g*32+31
    const int q    = w >> 1;         // column quarter: cols q*128 .. q*128+127
    const int ctaB0 = blockIdx.x * BTILE;

    // --- stage B operand: ALL 32 W1 rows (0-28 = X weights, 29-31 = feedback) ---
    for (int idx = tid; idx < SM_B_F2; idx += NTH) {
        const int kc = idx >> 11, rem = idx & 2047;
        const int col = rem >> 2, p = rem & 3;
        const int k0 = kc * 8 + p, k1 = k0 + 4;
        float2 fv;
        fv.x = __uint_as_float(tf32r(W1[k0 * K_HID + col]));
        fv.y = __uint_as_float(tf32r(W1[k1 * K_HID + col]));
        Bsm[idx] = fv;
    }
    // --- per-col-pair constants: (b1[c0], b1[c1], w2[c0], w2[c1]) ---
    for (int p = tid; p < K_HID / 2; p += NTH) {
        float4 c;
        c.x = b1[2 * p];
        c.y = b1[2 * p + 1];
        c.z = W2[2 * p];
        c.w = W2[2 * p + 1];
        cp4[p] = c;
    }
    // --- stage X(0) into buffer 0 (coalesced, tf32-rounded) ---
    #pragma unroll
    for (int k = 0; k < 8; ++k) {
        const int j = tid + k * NTH;
        if (j < XELEMS) {
            const int row = div29(j), col = j - row * F_IN;
            Xs[row * XSTRIDE + col] =
                __uint_as_float(tf32r(__ldg(X + (size_t)(ctaB0 + row) * TF_STR + col)));
        }
    }
    __syncthreads();

    // --- per-thread row bindings: 4 rows (rowL0 +0/+8/+16/+24) ---
    const int rowL0 = g * 32 + lg;
    const int rowG0 = ctaB0 + rowL0;
    float* __restrict__ outBase = out + (size_t)rowG0 * T_HOR;

    const float b2v = b2[0];

    float f0a = y0[rowG0 * 3 + 0],        f1a = y0[rowG0 * 3 + 1],        f2a = y0[rowG0 * 3 + 2];
    float f0b = y0[(rowG0 + 8) * 3 + 0],  f1b = y0[(rowG0 + 8) * 3 + 1],  f2b = y0[(rowG0 + 8) * 3 + 2];
    float f0c = y0[(rowG0 + 16) * 3 + 0], f1c = y0[(rowG0 + 16) * 3 + 1], f2c = y0[(rowG0 + 16) * 3 + 2];
    float f0d = y0[(rowG0 + 24) * 3 + 0], f1d = y0[(rowG0 + 24) * 3 + 1], f2d = y0[(rowG0 + 24) * 3 + 2];
    uint32_t fbA = tf32r((lq == 1) ? f0a : (lq == 2) ? f1a : f2a);
    uint32_t fbB = tf32r((lq == 1) ? f0b : (lq == 2) ? f1b : f2b);
    uint32_t fbC = tf32r((lq == 1) ? f0c : (lq == 2) ? f1c : f2c);
    uint32_t fbD = tf32r((lq == 1) ? f0d : (lq == 2) ? f1d : f2d);

    const int ntOfs = q * 16;               // this warp's n-tile offset (16 tiles = 128 cols)

    for (int t = 0; t < T_HOR; ++t) {
        const float* Xc = Xs + (t & 1) * XBUF;

        uint32_t a0[16], a1[16];
        loadA_sm(a0, Xc, rowL0, lq, fbA, fbB);
        loadA_sm(a1, Xc, rowL0 + 16, lq, fbC, fbD);

        // issue next step's X loads now; latency hidden under the nt loop
        uint32_t xr[8];
        const bool pf = (t + 1) < T_HOR;
        if (pf) {
            const float* __restrict__ src = X + (size_t)ctaB0 * TF_STR + (t + 1) * F_IN;
            #pragma unroll
            for (int k = 0; k < 8; ++k) {
                const int j = tid + k * NTH;
                if (j < XELEMS) {
                    const int row = div29(j), col = j - row * F_IN;
                    xr[k] = tf32r(__ldg(src + (size_t)row * TF_STR + col));
                }
            }
        }

        float dotA = 0.0f, dotB = 0.0f, dotC = 0.0f, dotD = 0.0f;

        #pragma unroll 4
        for (int nt = 0; nt < 16; ++nt) {
            const int ntg = ntOfs + nt;      // global n-tile (0..63)
            const float4 qc = cp4[ntg * 4 + lq];
            float d0 = qc.x, d1 = qc.y, d2 = qc.x, d3 = qc.y;   // set0 (bias-init)
            float e0 = qc.x, e1 = qc.y, e2 = qc.x, e3 = qc.y;   // set1
            #pragma unroll
            for (int kc = 0; kc < 4; ++kc) {
                const float2 bb = Bsm[kc * 2048 + ntg * 32 + lane];
                const uint32_t bx = __float_as_uint(bb.x), by = __float_as_uint(bb.y);
                MMA_TF32(d0, d1, d2, d3,
                         a0[kc * 4 + 0], a0[kc * 4 + 1], a0[kc * 4 + 2], a0[kc * 4 + 3], bx, by);
                MMA_TF32(e0, e1, e2, e3,
                         a1[kc * 4 + 0], a1[kc * 4 + 1], a1[kc * 4 + 2], a1[kc * 4 + 3], bx, by);
            }
            dotA = fmaf(tanh_fast(d0), qc.z, dotA);
            dotA = fmaf(tanh_fast(d1), qc.w, dotA);
            dotB = fmaf(tanh_fast(d2), qc.z, dotB);
            dotB = fmaf(tanh_fast(d3), qc.w, dotB);
            dotC = fmaf(tanh_fast(e0), qc.z, dotC);
            dotC = fmaf(tanh_fast(e1), qc.w, dotC);
            dotD = fmaf(tanh_fast(e2), qc.z, dotD);
            dotD = fmaf(tanh_fast(e3), qc.w, dotD);
        }

        // store staged X(t+1)
        if (pf) {
            float* __restrict__ Xn = Xs + ((t + 1) & 1) * XBUF;
            #pragma unroll
            for (int k = 0; k < 8; ++k) {
                const int j = tid + k * NTH;
                if (j < XELEMS) {
                    const int row = div29(j), col = j - row * F_IN;
                    Xn[row * XSTRIDE + col] = __uint_as_float(xr[k]);
                }
            }
        }

        // quad reduce (over the 8 cols each quad member covers)
        dotA += __shfl_xor_sync(0xffffffffu, dotA, 1);
        dotA += __shfl_xor_sync(0xffffffffu, dotA, 2);
        dotB += __shfl_xor_sync(0xffffffffu, dotB, 1);
        dotB += __shfl_xor_sync(0xffffffffu, dotB, 2);
        dotC += __shfl_xor_sync(0xffffffffu, dotC, 1);
        dotC += __shfl_xor_sync(0xffffffffu, dotC, 2);
        dotD += __shfl_xor_sync(0xffffffffu, dotD, 1);
        dotD += __shfl_xor_sync(0xffffffffu, dotD, 2);

        // cross-quarter combine via double-buffered SMEM partials + one barrier
        float* pbuf = part + (t & 1) * 256;
        if (lq == 0) {
            pbuf[q * 64 + rowL0]      = dotA;
            pbuf[q * 64 + rowL0 + 8]  = dotB;
            pbuf[q * 64 + rowL0 + 16] = dotC;
            pbuf[q * 64 + rowL0 + 24] = dotD;
        }
        __syncthreads();
        const float predA = pbuf[rowL0]      + pbuf[64 + rowL0]      + pbuf[128 + rowL0]      + pbuf[192 + rowL0]      + b2v;
        const float predB = pbuf[rowL0 + 8]  + pbuf[64 + rowL0 + 8]  + pbuf[128 + rowL0 + 8]  + pbuf[192 + rowL0 + 8]  + b2v;
        const float predC = pbuf[rowL0 + 16] + pbuf[64 + rowL0 + 16] + pbuf[128 + rowL0 + 16] + pbuf[192 + rowL0 + 16] + b2v;
        const float predD = pbuf[rowL0 + 24] + pbuf[64 + rowL0 + 24] + pbuf[128 + rowL0 + 24] + pbuf[192 + rowL0 + 24] + b2v;
        if (q == 0 && lq == 0) {
            outBase[t]              = predA;
            outBase[8 * T_HOR + t]  = predB;
            outBase[16 * T_HOR + t] = predC;
            outBase[24 * T_HOR + t] = predD;
        }
        // shift feedback: fb2 <- fb1 <- fb0 <- pred; refresh tf32 selections
        f2a = f1a; f1a = f0a; f0a = predA;
        f2b = f1b; f1b = f0b; f0b = predB;
        f2c = f1c; f1c = f0c; f0c = predC;
        f2d = f1d; f1d = f0d; f0d = predD;
        fbA = tf32r((lq == 1) ? f0a : (lq == 2) ? f1a : f2a);
        fbB = tf32r((lq == 1) ? f0b : (lq == 2) ? f1b : f2b);
        fbC = tf32r((lq == 1) ? f0c : (lq == 2) ? f1c : f2c);
        fbD = tf32r((lq == 1) ? f0d : (lq == 2) ? f1d : f2d);
    }
}

extern "C" void kernel_launch(void* const* d_in, const int* in_sizes, int n_in,
                              void* d_out, int out_size) {
    const float* X  = (const float*)d_in[0];
    const float* y0 = (const float*)d_in[1];
    const float* W1 = (const float*)d_in[2];
    const float* b1 = (const float*)d_in[3];
    const float* W2 = (const float*)d_in[4];
    const float* b2 = (const float*)d_in[5];
    float* out = (float*)d_out;
    (void)in_sizes; (void)n_in; (void)out_size;

    cudaFuncSetAttribute(narx_kernel, cudaFuncAttributeMaxDynamicSharedMemorySize, SM_TOTAL);
    narx_kernel<<<NCTAS, NTH, SM_TOTAL>>>(X, y0, W1, b1, W2, b2, out);
}